// round 13
// baseline (speedup 1.0000x reference)
#include <cuda_runtime.h>
#include <cuda_fp16.h>

#define D 64
#define MAXN 100000
#define MAXE 1600000
#define EPS 1e-5f
#define TILE_NODES 32   // nodes per block iteration (node kernel)
#define NPT 8           // nodes per 64-thread group (4 groups per block)

// Scratch: __device__ globals, 16B-aligned (float4 access)
__device__ __align__(16) float g_agg[(size_t)MAXN * D];
__device__ __align__(16) float g_xa[(size_t)MAXN * D];
__device__ __align__(16) float g_xb[(size_t)MAXN * D];
__device__ __align__(16) __half g_xh[(size_t)MAXN * D];  // fp16 gather payload
__device__ __align__(16) float g_ideg[MAXN];

// CSR-by-destination scratch
__device__ int g_count[MAXN];
__device__ int g_rowptr[MAXN + 1];
__device__ int g_cursor[MAXN];
__device__ int g_esrc[MAXE];
__device__ int g_bsum[256];

// ---------------------------------------------------------------------------
// CSR build
// ---------------------------------------------------------------------------
__global__ void zcnt_kernel(int n) {
    int i = blockIdx.x * blockDim.x + threadIdx.x;
    if (i < n) g_count[i] = 0;
}

__global__ void deg_kernel(const int* __restrict__ dst, int E) {
    int i = blockIdx.x * blockDim.x + threadIdx.x;
    if (i < E) atomicAdd(&g_count[dst[i]], 1);
}

// Phase A: per-block (1024 counts) sums
__global__ void scanA_kernel(int nNodes) {
    __shared__ int s[256];
    int b = blockIdx.x, t = threadIdx.x;
    int base = b * 1024 + t * 4;
    int tot = 0;
    #pragma unroll
    for (int k = 0; k < 4; k++)
        if (base + k < nNodes) tot += g_count[base + k];
    s[t] = tot;
    __syncthreads();
    for (int off = 128; off > 0; off >>= 1) {
        if (t < off) s[t] += s[t + off];
        __syncthreads();
    }
    if (t == 0) g_bsum[b] = s[0];
}

// Phase B: exclusive scan of block sums (single block, <=256 entries)
__global__ void scanB_kernel(int nb) {
    __shared__ int s[256];
    int t = threadIdx.x;
    s[t] = (t < nb) ? g_bsum[t] : 0;
    __syncthreads();
    for (int off = 1; off < 256; off <<= 1) {
        int y = (t >= off) ? s[t - off] : 0;
        __syncthreads();
        s[t] += y;
        __syncthreads();
    }
    g_bsum[t] = (t > 0) ? s[t - 1] : 0;
}

// Phase C: full exclusive scan -> rowptr + cursor + inv_deg
__global__ void scanC_kernel(int nNodes) {
    __shared__ int s[256];
    int b = blockIdx.x, t = threadIdx.x;
    int base = b * 1024 + t * 4;
    int c[4];
    #pragma unroll
    for (int k = 0; k < 4; k++)
        c[k] = (base + k < nNodes) ? g_count[base + k] : 0;
    int tot = c[0] + c[1] + c[2] + c[3];
    s[t] = tot;
    __syncthreads();
    for (int off = 1; off < 256; off <<= 1) {
        int y = (t >= off) ? s[t - off] : 0;
        __syncthreads();
        s[t] += y;
        __syncthreads();
    }
    int ex = ((t > 0) ? s[t - 1] : 0) + g_bsum[b];
    int p[4];
    p[0] = ex;
    p[1] = p[0] + c[0];
    p[2] = p[1] + c[1];
    p[3] = p[2] + c[2];
    #pragma unroll
    for (int k = 0; k < 4; k++) {
        int idx = base + k;
        if (idx <= nNodes) g_rowptr[idx] = p[k];
        if (idx < nNodes) {
            g_cursor[idx] = p[k];
            g_ideg[idx] = (c[k] > 0) ? (1.0f / (float)c[k]) : 0.0f;
        }
    }
}

__global__ void fill_kernel(const int* __restrict__ src,
                            const int* __restrict__ dst, int E) {
    int i = blockIdx.x * blockDim.x + threadIdx.x;
    if (i < E) {
        int d = dst[i];
        int p = atomicAdd(&g_cursor[d], 1);
        g_esrc[p] = src[i];
    }
}

// ---------------------------------------------------------------------------
// fp32 -> fp16 convert (layer-0 input only)
__global__ void conv_kernel(const float* __restrict__ x, int n2) {
    int i = blockIdx.x * blockDim.x + threadIdx.x;
    int stride = gridDim.x * blockDim.x;
    const float2* x2 = (const float2*)x;
    __half2* h2 = (__half2*)g_xh;
    for (int j = i; j < n2; j += stride)
        h2[j] = __float22half2_rn(x2[j]);
}

// ---------------------------------------------------------------------------
// Pull-mode aggregation over fp16 payload: 16-thread group per dst node.
// Thread c owns 4 half columns (8B); accumulate in fp32; 4-edge unroll.
// ---------------------------------------------------------------------------
__device__ __forceinline__ void acc_half4(float4& a, uint2 p) {
    __half2 h01 = *(__half2*)&p.x;
    __half2 h23 = *(__half2*)&p.y;
    float2 f01 = __half22float2(h01);
    float2 f23 = __half22float2(h23);
    a.x += f01.x; a.y += f01.y; a.z += f23.x; a.w += f23.y;
}

__global__ __launch_bounds__(256)
void agg_kernel(int nNodes) {
    const uint2* xh = (const uint2*)g_xh;   // 8B = 4 halves per thread-chunk
    int t = threadIdx.x;
    int c = t & 15;
    int g = t >> 4;
    int n = blockIdx.x * 16 + g;
    if (n >= nNodes) return;

    int start = g_rowptr[n];
    int end = g_rowptr[n + 1];

    float4 a0 = make_float4(0.f, 0.f, 0.f, 0.f);
    float4 a1 = make_float4(0.f, 0.f, 0.f, 0.f);
    float4 a2 = make_float4(0.f, 0.f, 0.f, 0.f);
    float4 a3 = make_float4(0.f, 0.f, 0.f, 0.f);
    int i = start;
    for (; i + 3 < end; i += 4) {
        int s0 = __ldg(&g_esrc[i]);
        int s1 = __ldg(&g_esrc[i + 1]);
        int s2 = __ldg(&g_esrc[i + 2]);
        int s3 = __ldg(&g_esrc[i + 3]);
        uint2 v0 = xh[(size_t)s0 * 16 + c];
        uint2 v1 = xh[(size_t)s1 * 16 + c];
        uint2 v2 = xh[(size_t)s2 * 16 + c];
        uint2 v3 = xh[(size_t)s3 * 16 + c];
        acc_half4(a0, v0);
        acc_half4(a1, v1);
        acc_half4(a2, v2);
        acc_half4(a3, v3);
    }
    for (; i < end; i++) {
        int s0 = __ldg(&g_esrc[i]);
        acc_half4(a0, xh[(size_t)s0 * 16 + c]);
    }
    float id = g_ideg[n];
    float4 r = make_float4((a0.x + a1.x + a2.x + a3.x) * id,
                           (a0.y + a1.y + a2.y + a3.y) * id,
                           (a0.z + a1.z + a2.z + a3.z) * id,
                           (a0.w + a1.w + a2.w + a3.w) * id);
    // agg rows are 16 float4 per node; thread c writes its owned 16B slot
    ((float4*)g_agg)[(size_t)n * 16 + c] = r;
}

// ---------------------------------------------------------------------------
// Fused node kernel, register-tiled.
// MODE 0: L0, in=ext x, out=g_xa (+fp16 shadow), residual = x@w_res+b_res.
// MODE 1: L1, in=g_xa, out=g_xb (+fp16 shadow), residual = input.
// MODE 2: L2+FC, in=g_xb, writes ext_out = (LN-out) @ w_fc + b_fc.
template <int MODE>
__global__ __launch_bounds__(256)
void node_kernel(const float* __restrict__ ext_in,
                 float* __restrict__ ext_out,
                 const float* __restrict__ wl,
                 const float* __restrict__ bl,
                 const float* __restrict__ wr,
                 const float* __restrict__ gamma,
                 const float* __restrict__ beta,
                 const float* __restrict__ we,
                 const float* __restrict__ be,
                 int nNodes) {
    const float* x = (MODE == 0) ? ext_in : (MODE == 1 ? (const float*)g_xa
                                                       : (const float*)g_xb);
    float* xout = (MODE == 0) ? g_xa : (MODE == 1 ? g_xb : ext_out);

    extern __shared__ __align__(16) float sW[];   // sWl[64][64], sWr[64][64]
    float* sWl = sW;
    float* sWr = sW + D * D;
    __shared__ __align__(16) float sX[TILE_NODES][D];
    __shared__ __align__(16) float sA[TILE_NODES][D];
    __shared__ float sRed[4][2][NPT][2];
    __shared__ __align__(16) float sWe[(MODE != 1) ? (D * D) : 4];

    int tid = threadIdx.x;

    for (int i = tid; i < (D * D) / 4; i += 256) {
        ((float4*)sWl)[i] = ((const float4*)wl)[i];
        ((float4*)sWr)[i] = ((const float4*)wr)[i];
        if (MODE != 1) ((float4*)sWe)[i] = ((const float4*)we)[i];
    }

    int col = tid & 63;
    int grp = tid >> 6;
    int lane = tid & 31;
    int half = (tid >> 5) & 1;
    int nb = grp * NPT;

    float blv = bl[col];
    float gv = gamma[col];
    float bev = beta[col];
    float bev2 = (MODE != 1) ? be[col] : 0.f;

    int numTiles = (nNodes + TILE_NODES - 1) / TILE_NODES;
    for (int tile = blockIdx.x; tile < numTiles; tile += gridDim.x) {
        int base = tile * TILE_NODES;

        __syncthreads();
        for (int i = tid; i < (TILE_NODES * D) / 4; i += 256) {
            int row = base + (i >> 4);
            float4 xv = make_float4(0.f, 0.f, 0.f, 0.f);
            float4 av = xv;
            if (row < nNodes) {
                size_t o4 = (size_t)row * (D / 4) + (i & 15);
                xv = ((const float4*)x)[o4];
                av = ((const float4*)g_agg)[o4];
            }
            ((float4*)sX)[i] = xv;
            ((float4*)sA)[i] = av;
        }
        __syncthreads();

        float acc[NPT], acc2[NPT];
        #pragma unroll
        for (int j = 0; j < NPT; j++) {
            acc[j] = blv;
            acc2[j] = (MODE == 0) ? bev2 : 0.f;
        }

        #pragma unroll 4
        for (int k4 = 0; k4 < D / 4; k4++) {
            int k = k4 * 4;
            float wl0 = sWl[(k + 0) * D + col];
            float wl1 = sWl[(k + 1) * D + col];
            float wl2 = sWl[(k + 2) * D + col];
            float wl3 = sWl[(k + 3) * D + col];
            float wr0 = sWr[(k + 0) * D + col];
            float wr1 = sWr[(k + 1) * D + col];
            float wr2 = sWr[(k + 2) * D + col];
            float wr3 = sWr[(k + 3) * D + col];
            float we0, we1, we2, we3;
            if (MODE == 0) {
                we0 = sWe[(k + 0) * D + col];
                we1 = sWe[(k + 1) * D + col];
                we2 = sWe[(k + 2) * D + col];
                we3 = sWe[(k + 3) * D + col];
            }
            #pragma unroll
            for (int j = 0; j < NPT; j++) {
                float4 a = ((const float4*)sA[nb + j])[k4];
                float4 xx = ((const float4*)sX[nb + j])[k4];
                acc[j] = fmaf(a.x, wl0, acc[j]);
                acc[j] = fmaf(a.y, wl1, acc[j]);
                acc[j] = fmaf(a.z, wl2, acc[j]);
                acc[j] = fmaf(a.w, wl3, acc[j]);
                acc[j] = fmaf(xx.x, wr0, acc[j]);
                acc[j] = fmaf(xx.y, wr1, acc[j]);
                acc[j] = fmaf(xx.z, wr2, acc[j]);
                acc[j] = fmaf(xx.w, wr3, acc[j]);
                if (MODE == 0) {
                    acc2[j] = fmaf(xx.x, we0, acc2[j]);
                    acc2[j] = fmaf(xx.y, we1, acc2[j]);
                    acc2[j] = fmaf(xx.z, we2, acc2[j]);
                    acc2[j] = fmaf(xx.w, we3, acc2[j]);
                }
            }
        }

        #pragma unroll
        for (int j = 0; j < NPT; j++) {
            float s = acc[j], s2 = acc[j] * acc[j];
            #pragma unroll
            for (int o = 16; o > 0; o >>= 1) {
                s += __shfl_xor_sync(0xFFFFFFFFu, s, o);
                s2 += __shfl_xor_sync(0xFFFFFFFFu, s2, o);
            }
            if (lane == 0) {
                sRed[grp][half][j][0] = s;
                sRed[grp][half][j][1] = s2;
            }
        }
        __syncthreads();

        #pragma unroll
        for (int j = 0; j < NPT; j++) {
            float sum = sRed[grp][0][j][0] + sRed[grp][1][j][0];
            float sum2 = sRed[grp][0][j][1] + sRed[grp][1][j][1];
            float mu = sum * (1.0f / 64.0f);
            float var = sum2 * (1.0f / 64.0f) - mu * mu;
            float rstd = rsqrtf(var + EPS);
            float y = (acc[j] - mu) * rstd * gv + bev;
            y = fmaxf(y, 0.f);
            if (MODE == 0) y += acc2[j];
            else           y += sX[nb + j][col];

            if (MODE != 2) {
                int n = base + nb + j;
                if (n < nNodes) {
                    xout[(size_t)n * D + col] = y;
                    g_xh[(size_t)n * D + col] = __float2half_rn(y);
                }
            } else {
                sA[nb + j][col] = y;
            }
        }

        if (MODE == 2) {
            __syncthreads();
            float acc3[NPT];
            #pragma unroll
            for (int j = 0; j < NPT; j++) acc3[j] = bev2;
            #pragma unroll 4
            for (int k4 = 0; k4 < D / 4; k4++) {
                int k = k4 * 4;
                float w0 = sWe[(k + 0) * D + col];
                float w1 = sWe[(k + 1) * D + col];
                float w2 = sWe[(k + 2) * D + col];
                float w3 = sWe[(k + 3) * D + col];
                #pragma unroll
                for (int j = 0; j < NPT; j++) {
                    float4 yy = ((const float4*)sA[nb + j])[k4];
                    acc3[j] = fmaf(yy.x, w0, acc3[j]);
                    acc3[j] = fmaf(yy.y, w1, acc3[j]);
                    acc3[j] = fmaf(yy.z, w2, acc3[j]);
                    acc3[j] = fmaf(yy.w, w3, acc3[j]);
                }
            }
            #pragma unroll
            for (int j = 0; j < NPT; j++) {
                int n = base + nb + j;
                if (n < nNodes) xout[(size_t)n * D + col] = acc3[j];
            }
        }
    }
}

// ---------------------------------------------------------------------------
extern "C" void kernel_launch(void* const* d_in, const int* in_sizes, int n_in,
                              void* d_out, int out_size) {
    const float* x     = (const float*)d_in[0];
    const int*   esrc  = (const int*)d_in[1];
    const int*   edst  = (const int*)d_in[2];
    const float* w_l   = (const float*)d_in[3];
    const float* b_l   = (const float*)d_in[4];
    const float* w_r   = (const float*)d_in[5];
    const float* gamma = (const float*)d_in[6];
    const float* beta  = (const float*)d_in[7];
    const float* w_res = (const float*)d_in[8];
    const float* b_res = (const float*)d_in[9];
    const float* w_fc  = (const float*)d_in[10];
    const float* b_fc  = (const float*)d_in[11];
    float* out = (float*)d_out;

    int N = in_sizes[0] / D;
    int E = in_sizes[1];

    const int T = 256;
    const size_t SMEM_NODE = 2 * D * D * sizeof(float);  // 32KB dynamic
    const int BLK_FUSED = 444;   // 3 blocks/SM at ~65KB total smem
    const int BLK_MID   = 592;   // 4 blocks/SM at ~49KB total smem
    int NB = (N + 1 + 1023) / 1024;
    int aggBlocks = (N + 15) / 16;

    static bool attr_done = false;
    if (!attr_done) {
        cudaFuncSetAttribute(node_kernel<0>,
                             cudaFuncAttributeMaxDynamicSharedMemorySize,
                             (int)SMEM_NODE);
        cudaFuncSetAttribute(node_kernel<1>,
                             cudaFuncAttributeMaxDynamicSharedMemorySize,
                             (int)SMEM_NODE);
        cudaFuncSetAttribute(node_kernel<2>,
                             cudaFuncAttributeMaxDynamicSharedMemorySize,
                             (int)SMEM_NODE);
        attr_done = true;
    }

    // --- CSR build (once per call) + fp16 convert of layer-0 input ---
    zcnt_kernel<<<(N + T - 1) / T, T>>>(N);
    conv_kernel<<<1184, T>>>(x, (N * D) / 2);
    deg_kernel<<<(E + T - 1) / T, T>>>(edst, E);
    scanA_kernel<<<NB, T>>>(N);
    scanB_kernel<<<1, T>>>(NB);
    scanC_kernel<<<NB, T>>>(N);
    fill_kernel<<<(E + T - 1) / T, T>>>(esrc, edst, E);

    // Layer 0: pull-aggregate(fp16 x); node (fused residual proj) -> g_xa
    agg_kernel<<<aggBlocks, T>>>(N);
    node_kernel<0><<<BLK_FUSED, T, SMEM_NODE>>>(
        x, nullptr, w_l, b_l, w_r, gamma, beta, w_res, b_res, N);

    // Layer 1: g_xa -> g_xb
    agg_kernel<<<aggBlocks, T>>>(N);
    node_kernel<1><<<BLK_MID, T, SMEM_NODE>>>(
        nullptr, nullptr, w_l + D * D, b_l + D, w_r + D * D,
        gamma + D, beta + D, nullptr, nullptr, N);

    // Layer 2 + final FC: writes d_out directly
    agg_kernel<<<aggBlocks, T>>>(N);
    node_kernel<2><<<BLK_FUSED, T, SMEM_NODE>>>(
        nullptr, out, w_l + 2 * D * D, b_l + 2 * D, w_r + 2 * D * D,
        gamma + 2 * D, beta + 2 * D, w_fc, b_fc, N);
}

// round 14
// speedup vs baseline: 1.0582x; 1.0582x over previous
#include <cuda_runtime.h>
#include <cuda_fp16.h>

#define D 64
#define MAXN 100000
#define MAXE 1600000
#define EPS 1e-5f
#define TILE_NODES 32   // nodes per block iteration (node kernel)
#define NPT 8           // nodes per 64-thread group (4 groups per block)

// Scratch: __device__ globals, 16B-aligned (float4/uint4 access)
__device__ __align__(16) float g_agg[(size_t)MAXN * D];
__device__ __align__(16) float g_xa[(size_t)MAXN * D];
__device__ __align__(16) float g_xb[(size_t)MAXN * D];
__device__ __align__(16) __half g_xh[(size_t)MAXN * D];  // fp16 gather payload
__device__ __align__(16) float g_ideg[MAXN];

// CSR-by-destination scratch
__device__ int g_count[MAXN];
__device__ int g_rowptr[MAXN + 1];
__device__ int g_cursor[MAXN];
__device__ int g_esrc[MAXE];
__device__ int g_bsum[256];

// ---------------------------------------------------------------------------
// CSR build
// ---------------------------------------------------------------------------
// Fused: zero counts + fp32->fp16 convert of layer-0 input
__global__ void prep_kernel(const float* __restrict__ x, int n2, int nNodes) {
    int i = blockIdx.x * blockDim.x + threadIdx.x;
    int stride = gridDim.x * blockDim.x;
    const float2* x2 = (const float2*)x;
    __half2* h2 = (__half2*)g_xh;
    for (int j = i; j < n2; j += stride)
        h2[j] = __float22half2_rn(x2[j]);
    for (int j = i; j < nNodes; j += stride)
        g_count[j] = 0;
}

__global__ void deg_kernel(const int* __restrict__ dst, int E) {
    int i = blockIdx.x * blockDim.x + threadIdx.x;
    if (i < E) atomicAdd(&g_count[dst[i]], 1);
}

// Phase A: per-block (1024 counts) sums
__global__ void scanA_kernel(int nNodes) {
    __shared__ int s[256];
    int b = blockIdx.x, t = threadIdx.x;
    int base = b * 1024 + t * 4;
    int tot = 0;
    #pragma unroll
    for (int k = 0; k < 4; k++)
        if (base + k < nNodes) tot += g_count[base + k];
    s[t] = tot;
    __syncthreads();
    for (int off = 128; off > 0; off >>= 1) {
        if (t < off) s[t] += s[t + off];
        __syncthreads();
    }
    if (t == 0) g_bsum[b] = s[0];
}

// Phase B: exclusive scan of block sums (single block, <=256 entries)
__global__ void scanB_kernel(int nb) {
    __shared__ int s[256];
    int t = threadIdx.x;
    s[t] = (t < nb) ? g_bsum[t] : 0;
    __syncthreads();
    for (int off = 1; off < 256; off <<= 1) {
        int y = (t >= off) ? s[t - off] : 0;
        __syncthreads();
        s[t] += y;
        __syncthreads();
    }
    g_bsum[t] = (t > 0) ? s[t - 1] : 0;
}

// Phase C: full exclusive scan -> rowptr + cursor + inv_deg
__global__ void scanC_kernel(int nNodes) {
    __shared__ int s[256];
    int b = blockIdx.x, t = threadIdx.x;
    int base = b * 1024 + t * 4;
    int c[4];
    #pragma unroll
    for (int k = 0; k < 4; k++)
        c[k] = (base + k < nNodes) ? g_count[base + k] : 0;
    int tot = c[0] + c[1] + c[2] + c[3];
    s[t] = tot;
    __syncthreads();
    for (int off = 1; off < 256; off <<= 1) {
        int y = (t >= off) ? s[t - off] : 0;
        __syncthreads();
        s[t] += y;
        __syncthreads();
    }
    int ex = ((t > 0) ? s[t - 1] : 0) + g_bsum[b];
    int p[4];
    p[0] = ex;
    p[1] = p[0] + c[0];
    p[2] = p[1] + c[1];
    p[3] = p[2] + c[2];
    #pragma unroll
    for (int k = 0; k < 4; k++) {
        int idx = base + k;
        if (idx <= nNodes) g_rowptr[idx] = p[k];
        if (idx < nNodes) {
            g_cursor[idx] = p[k];
            g_ideg[idx] = (c[k] > 0) ? (1.0f / (float)c[k]) : 0.0f;
        }
    }
}

__global__ void fill_kernel(const int* __restrict__ src,
                            const int* __restrict__ dst, int E) {
    int i = blockIdx.x * blockDim.x + threadIdx.x;
    if (i < E) {
        int d = dst[i];
        int p = atomicAdd(&g_cursor[d], 1);
        g_esrc[p] = src[i];
    }
}

// ---------------------------------------------------------------------------
// Pull-mode aggregation over fp16 payload: 8-thread group per dst node.
// Each thread owns one uint4 = 8 half columns (16B) -> 8 loads per edge
// (was 16 in the fp32 version), halving both load-issue count and bytes.
// Accumulate in fp32; 4-edge unroll for MLP.
// ---------------------------------------------------------------------------
__device__ __forceinline__ void acc8(float* a, uint4 v) {
    float2 f;
    f = __half22float2(*(__half2*)&v.x); a[0] += f.x; a[1] += f.y;
    f = __half22float2(*(__half2*)&v.y); a[2] += f.x; a[3] += f.y;
    f = __half22float2(*(__half2*)&v.z); a[4] += f.x; a[5] += f.y;
    f = __half22float2(*(__half2*)&v.w); a[6] += f.x; a[7] += f.y;
}

__global__ __launch_bounds__(256)
void agg_kernel(int nNodes) {
    const uint4* xh = (const uint4*)g_xh;   // 8 uint4 per node row
    int t = threadIdx.x;
    int c = t & 7;        // 16B chunk within row
    int g = t >> 3;       // node group within block (32 per block)
    int n = blockIdx.x * 32 + g;
    if (n >= nNodes) return;

    int start = g_rowptr[n];
    int end = g_rowptr[n + 1];

    float acc[8];
    #pragma unroll
    for (int k = 0; k < 8; k++) acc[k] = 0.f;

    int i = start;
    for (; i + 3 < end; i += 4) {
        int s0 = __ldg(&g_esrc[i]);
        int s1 = __ldg(&g_esrc[i + 1]);
        int s2 = __ldg(&g_esrc[i + 2]);
        int s3 = __ldg(&g_esrc[i + 3]);
        uint4 v0 = xh[(size_t)s0 * 8 + c];
        uint4 v1 = xh[(size_t)s1 * 8 + c];
        uint4 v2 = xh[(size_t)s2 * 8 + c];
        uint4 v3 = xh[(size_t)s3 * 8 + c];
        acc8(acc, v0);
        acc8(acc, v1);
        acc8(acc, v2);
        acc8(acc, v3);
    }
    for (; i < end; i++) {
        int s0 = __ldg(&g_esrc[i]);
        acc8(acc, xh[(size_t)s0 * 8 + c]);
    }

    float id = g_ideg[n];
    float4 r0 = make_float4(acc[0] * id, acc[1] * id, acc[2] * id, acc[3] * id);
    float4 r1 = make_float4(acc[4] * id, acc[5] * id, acc[6] * id, acc[7] * id);
    ((float4*)g_agg)[(size_t)n * 16 + c * 2] = r0;
    ((float4*)g_agg)[(size_t)n * 16 + c * 2 + 1] = r1;
}

// ---------------------------------------------------------------------------
// Fused node kernel, register-tiled.
// MODE 0: L0, in=ext x, out=g_xa (+fp16 shadow), residual = x@w_res+b_res.
// MODE 1: L1, in=g_xa, out=g_xb (+fp16 shadow), residual = input.
// MODE 2: L2+FC, in=g_xb, writes ext_out = (LN-out) @ w_fc + b_fc.
template <int MODE>
__global__ __launch_bounds__(256)
void node_kernel(const float* __restrict__ ext_in,
                 float* __restrict__ ext_out,
                 const float* __restrict__ wl,
                 const float* __restrict__ bl,
                 const float* __restrict__ wr,
                 const float* __restrict__ gamma,
                 const float* __restrict__ beta,
                 const float* __restrict__ we,
                 const float* __restrict__ be,
                 int nNodes) {
    const float* x = (MODE == 0) ? ext_in : (MODE == 1 ? (const float*)g_xa
                                                       : (const float*)g_xb);
    float* xout = (MODE == 0) ? g_xa : (MODE == 1 ? g_xb : ext_out);

    extern __shared__ __align__(16) float sW[];   // sWl[64][64], sWr[64][64]
    float* sWl = sW;
    float* sWr = sW + D * D;
    __shared__ __align__(16) float sX[TILE_NODES][D];
    __shared__ __align__(16) float sA[TILE_NODES][D];
    __shared__ float sRed[4][2][NPT][2];
    __shared__ __align__(16) float sWe[(MODE != 1) ? (D * D) : 4];

    int tid = threadIdx.x;

    for (int i = tid; i < (D * D) / 4; i += 256) {
        ((float4*)sWl)[i] = ((const float4*)wl)[i];
        ((float4*)sWr)[i] = ((const float4*)wr)[i];
        if (MODE != 1) ((float4*)sWe)[i] = ((const float4*)we)[i];
    }

    int col = tid & 63;
    int grp = tid >> 6;
    int lane = tid & 31;
    int half = (tid >> 5) & 1;
    int nb = grp * NPT;

    float blv = bl[col];
    float gv = gamma[col];
    float bev = beta[col];
    float bev2 = (MODE != 1) ? be[col] : 0.f;

    int numTiles = (nNodes + TILE_NODES - 1) / TILE_NODES;
    for (int tile = blockIdx.x; tile < numTiles; tile += gridDim.x) {
        int base = tile * TILE_NODES;

        __syncthreads();
        for (int i = tid; i < (TILE_NODES * D) / 4; i += 256) {
            int row = base + (i >> 4);
            float4 xv = make_float4(0.f, 0.f, 0.f, 0.f);
            float4 av = xv;
            if (row < nNodes) {
                size_t o4 = (size_t)row * (D / 4) + (i & 15);
                xv = ((const float4*)x)[o4];
                av = ((const float4*)g_agg)[o4];
            }
            ((float4*)sX)[i] = xv;
            ((float4*)sA)[i] = av;
        }
        __syncthreads();

        float acc[NPT], acc2[NPT];
        #pragma unroll
        for (int j = 0; j < NPT; j++) {
            acc[j] = blv;
            acc2[j] = (MODE == 0) ? bev2 : 0.f;
        }

        #pragma unroll 4
        for (int k4 = 0; k4 < D / 4; k4++) {
            int k = k4 * 4;
            float wl0 = sWl[(k + 0) * D + col];
            float wl1 = sWl[(k + 1) * D + col];
            float wl2 = sWl[(k + 2) * D + col];
            float wl3 = sWl[(k + 3) * D + col];
            float wr0 = sWr[(k + 0) * D + col];
            float wr1 = sWr[(k + 1) * D + col];
            float wr2 = sWr[(k + 2) * D + col];
            float wr3 = sWr[(k + 3) * D + col];
            float we0, we1, we2, we3;
            if (MODE == 0) {
                we0 = sWe[(k + 0) * D + col];
                we1 = sWe[(k + 1) * D + col];
                we2 = sWe[(k + 2) * D + col];
                we3 = sWe[(k + 3) * D + col];
            }
            #pragma unroll
            for (int j = 0; j < NPT; j++) {
                float4 a = ((const float4*)sA[nb + j])[k4];
                float4 xx = ((const float4*)sX[nb + j])[k4];
                acc[j] = fmaf(a.x, wl0, acc[j]);
                acc[j] = fmaf(a.y, wl1, acc[j]);
                acc[j] = fmaf(a.z, wl2, acc[j]);
                acc[j] = fmaf(a.w, wl3, acc[j]);
                acc[j] = fmaf(xx.x, wr0, acc[j]);
                acc[j] = fmaf(xx.y, wr1, acc[j]);
                acc[j] = fmaf(xx.z, wr2, acc[j]);
                acc[j] = fmaf(xx.w, wr3, acc[j]);
                if (MODE == 0) {
                    acc2[j] = fmaf(xx.x, we0, acc2[j]);
                    acc2[j] = fmaf(xx.y, we1, acc2[j]);
                    acc2[j] = fmaf(xx.z, we2, acc2[j]);
                    acc2[j] = fmaf(xx.w, we3, acc2[j]);
                }
            }
        }

        #pragma unroll
        for (int j = 0; j < NPT; j++) {
            float s = acc[j], s2 = acc[j] * acc[j];
            #pragma unroll
            for (int o = 16; o > 0; o >>= 1) {
                s += __shfl_xor_sync(0xFFFFFFFFu, s, o);
                s2 += __shfl_xor_sync(0xFFFFFFFFu, s2, o);
            }
            if (lane == 0) {
                sRed[grp][half][j][0] = s;
                sRed[grp][half][j][1] = s2;
            }
        }
        __syncthreads();

        #pragma unroll
        for (int j = 0; j < NPT; j++) {
            float sum = sRed[grp][0][j][0] + sRed[grp][1][j][0];
            float sum2 = sRed[grp][0][j][1] + sRed[grp][1][j][1];
            float mu = sum * (1.0f / 64.0f);
            float var = sum2 * (1.0f / 64.0f) - mu * mu;
            float rstd = rsqrtf(var + EPS);
            float y = (acc[j] - mu) * rstd * gv + bev;
            y = fmaxf(y, 0.f);
            if (MODE == 0) y += acc2[j];
            else           y += sX[nb + j][col];

            if (MODE != 2) {
                int n = base + nb + j;
                if (n < nNodes) {
                    xout[(size_t)n * D + col] = y;
                    g_xh[(size_t)n * D + col] = __float2half_rn(y);
                }
            } else {
                sA[nb + j][col] = y;
            }
        }

        if (MODE == 2) {
            __syncthreads();
            float acc3[NPT];
            #pragma unroll
            for (int j = 0; j < NPT; j++) acc3[j] = bev2;
            #pragma unroll 4
            for (int k4 = 0; k4 < D / 4; k4++) {
                int k = k4 * 4;
                float w0 = sWe[(k + 0) * D + col];
                float w1 = sWe[(k + 1) * D + col];
                float w2 = sWe[(k + 2) * D + col];
                float w3 = sWe[(k + 3) * D + col];
                #pragma unroll
                for (int j = 0; j < NPT; j++) {
                    float4 yy = ((const float4*)sA[nb + j])[k4];
                    acc3[j] = fmaf(yy.x, w0, acc3[j]);
                    acc3[j] = fmaf(yy.y, w1, acc3[j]);
                    acc3[j] = fmaf(yy.z, w2, acc3[j]);
                    acc3[j] = fmaf(yy.w, w3, acc3[j]);
                }
            }
            #pragma unroll
            for (int j = 0; j < NPT; j++) {
                int n = base + nb + j;
                if (n < nNodes) xout[(size_t)n * D + col] = acc3[j];
            }
        }
    }
}

// ---------------------------------------------------------------------------
extern "C" void kernel_launch(void* const* d_in, const int* in_sizes, int n_in,
                              void* d_out, int out_size) {
    const float* x     = (const float*)d_in[0];
    const int*   esrc  = (const int*)d_in[1];
    const int*   edst  = (const int*)d_in[2];
    const float* w_l   = (const float*)d_in[3];
    const float* b_l   = (const float*)d_in[4];
    const float* w_r   = (const float*)d_in[5];
    const float* gamma = (const float*)d_in[6];
    const float* beta  = (const float*)d_in[7];
    const float* w_res = (const float*)d_in[8];
    const float* b_res = (const float*)d_in[9];
    const float* w_fc  = (const float*)d_in[10];
    const float* b_fc  = (const float*)d_in[11];
    float* out = (float*)d_out;

    int N = in_sizes[0] / D;
    int E = in_sizes[1];

    const int T = 256;
    const size_t SMEM_NODE = 2 * D * D * sizeof(float);  // 32KB dynamic
    const int BLK_FUSED = 444;   // 3 blocks/SM at ~65KB total smem
    const int BLK_MID   = 592;   // 4 blocks/SM at ~49KB total smem
    int NB = (N + 1 + 1023) / 1024;
    int aggBlocks = (N + 31) / 32;

    static bool attr_done = false;
    if (!attr_done) {
        cudaFuncSetAttribute(node_kernel<0>,
                             cudaFuncAttributeMaxDynamicSharedMemorySize,
                             (int)SMEM_NODE);
        cudaFuncSetAttribute(node_kernel<1>,
                             cudaFuncAttributeMaxDynamicSharedMemorySize,
                             (int)SMEM_NODE);
        cudaFuncSetAttribute(node_kernel<2>,
                             cudaFuncAttributeMaxDynamicSharedMemorySize,
                             (int)SMEM_NODE);
        attr_done = true;
    }

    // --- CSR build + fp16 convert of layer-0 input ---
    prep_kernel<<<1184, T>>>(x, (N * D) / 2, N);
    deg_kernel<<<(E + T - 1) / T, T>>>(edst, E);
    scanA_kernel<<<NB, T>>>(N);
    scanB_kernel<<<1, T>>>(NB);
    scanC_kernel<<<NB, T>>>(N);
    fill_kernel<<<(E + T - 1) / T, T>>>(esrc, edst, E);

    // Layer 0: pull-aggregate(fp16 x); node (fused residual proj) -> g_xa
    agg_kernel<<<aggBlocks, T>>>(N);
    node_kernel<0><<<BLK_FUSED, T, SMEM_NODE>>>(
        x, nullptr, w_l, b_l, w_r, gamma, beta, w_res, b_res, N);

    // Layer 1: g_xa -> g_xb
    agg_kernel<<<aggBlocks, T>>>(N);
    node_kernel<1><<<BLK_MID, T, SMEM_NODE>>>(
        nullptr, nullptr, w_l + D * D, b_l + D, w_r + D * D,
        gamma + D, beta + D, nullptr, nullptr, N);

    // Layer 2 + final FC: writes d_out directly
    agg_kernel<<<aggBlocks, T>>>(N);
    node_kernel<2><<<BLK_FUSED, T, SMEM_NODE>>>(
        nullptr, out, w_l + 2 * D * D, b_l + 2 * D, w_r + 2 * D * D,
        gamma + 2 * D, beta + 2 * D, w_fc, b_fc, N);
}